// round 15
// baseline (speedup 1.0000x reference)
#include <cuda_runtime.h>
#include <cuda_fp16.h>
#include <math.h>

// ---------------------------------------------------------------------------
// VQ-VAE forward.  B=16, L=156, P=8, H=W=128, codebook 512x8.
// R15: d3 as a single MT=160 (NT=10) launch -- one slab staging per row
//      serves all 160 co (was staged twice at MT=80 grid.y=2).
//      Accumulation order per output unchanged -> bit-identical numerics.
// ---------------------------------------------------------------------------

#define BATCH 16
#define HW    16384   // 128*128

__device__ __forceinline__ void mma_f16(float c[4], const unsigned a[4], uint2 b) {
    asm volatile("mma.sync.aligned.m16n8k16.row.col.f32.f16.f16.f32 "
        "{%0,%1,%2,%3}, {%4,%5,%6,%7}, {%8,%9}, {%0,%1,%2,%3};"
        : "+f"(c[0]), "+f"(c[1]), "+f"(c[2]), "+f"(c[3])
        : "r"(a[0]), "r"(a[1]), "r"(a[2]), "r"(a[3]), "r"(b.x), "r"(b.y));
}
__device__ __forceinline__ void ldsm4(unsigned a[4], unsigned addr) {
    asm volatile("ldmatrix.sync.aligned.m8n8.x4.shared.b16 {%0,%1,%2,%3}, [%4];"
        : "=r"(a[0]), "=r"(a[1]), "=r"(a[2]), "=r"(a[3]) : "r"(addr));
}
__device__ __forceinline__ unsigned h2u(float lo, float hi) {
    __half2 h = __floats2half2_rn(lo, hi);
    return *(unsigned*)&h;
}

// Static device scratch.  Activations NHWC16: [n][chunk][h][w][16ch] fp16,
// stored as u32 (half2); 8 u32 per pixel per chunk.
__device__ unsigned g_x16[BATCH * 10 * HW * 8];
__device__ unsigned g_z1h[BATCH *  8 * HW * 8];
__device__ unsigned g_z2h[BATCH *  4 * HW * 8];
__device__ float    g_z3 [BATCH *  8 * HW];      // fp32 NCHW for VQ
__device__ unsigned g_qh [BATCH *  1 * HW * 8];  // ch 8..15 zeroed by VQ
__device__ unsigned g_y1h[BATCH *  4 * HW * 8];
__device__ unsigned g_y2h[BATCH *  8 * HW * 8];
// fp16 weights: [chunk16][tap 9][CO_PAD][slot 8]; slot s -> ci pair
// (2p, 2p+1), p = (s&1)?(s>>1)+4:(s>>1)  (matches mma B fragment k-order).
__device__ unsigned g_w_e1[10 * 9 * 128 * 8];
__device__ unsigned g_w_e2[ 8 * 9 *  64 * 8];
__device__ unsigned g_w_e3[ 4 * 9 *  16 * 8];
__device__ unsigned g_w_d1[ 1 * 9 *  64 * 8];
__device__ unsigned g_w_d2[ 4 * 9 * 128 * 8];
__device__ unsigned g_w_d3[ 8 * 9 * 160 * 8];
__device__ double   g_part[256];

// ---------------------------------------------------------------------------
__device__ void pack16(const float* __restrict__ w, unsigned* __restrict__ out,
                       int CIN, int COUT, int CO_PAD, int transposed, int idx) {
    int s     = idx & 7;
    int co    = (idx >> 3) % CO_PAD;
    int tap   = ((idx >> 3) / CO_PAD) % 9;
    int chunk = ((idx >> 3) / CO_PAD) / 9;
    int p     = (s & 1) ? (s >> 1) + 4 : (s >> 1);
    int ci0   = chunk * 16 + 2 * p, ci1 = ci0 + 1;
    float v0 = 0.f, v1 = 0.f;
    if (co < COUT) {
        if (transposed) {
            if (ci0 < CIN) v0 = w[((size_t)ci0 * COUT + co) * 9 + (8 - tap)];
            if (ci1 < CIN) v1 = w[((size_t)ci1 * COUT + co) * 9 + (8 - tap)];
        } else {
            if (ci0 < CIN) v0 = w[((size_t)co * CIN + ci0) * 9 + tap];
            if (ci1 < CIN) v1 = w[((size_t)co * CIN + ci1) * 9 + tap];
        }
    }
    out[idx] = h2u(v0, v1);
}

__global__ void pack_all(const float* e1w, const float* e2w, const float* e3w,
                         const float* d1w, const float* d2w, const float* d3w,
                         unsigned* we1, unsigned* we2, unsigned* we3,
                         unsigned* wd1, unsigned* wd2, unsigned* wd3) {
    int idx = blockIdx.x * 256 + threadIdx.x;
    if (idx < 92160) { pack16(e1w, we1, 156, 128, 128, 0, idx); return; }
    idx -= 92160;
    if (idx < 36864) { pack16(e2w, we2, 128,  64,  64, 0, idx); return; }
    idx -= 36864;
    if (idx < 4608)  { pack16(e3w, we3,  64,   8,  16, 0, idx); return; }
    idx -= 4608;
    if (idx < 4608)  { pack16(d1w, wd1,   8,  64,  64, 1, idx); return; }
    idx -= 4608;
    if (idx < 36864) { pack16(d2w, wd2,  64, 128, 128, 1, idx); return; }
    idx -= 36864;
    if (idx < 92160) { pack16(d3w, wd3, 128, 156, 160, 1, idx); }
}

// x (fp32 NCHW, 156 ch) -> NHWC16 fp16, ch 156..159 zero.
__global__ void x_to_nhwc(const float* __restrict__ x, unsigned* __restrict__ x16) {
    int i = blockIdx.x * 256 + threadIdx.x;
    const int total = BATCH * 10 * HW;
    if (i >= total) return;
    int hw   = i & 16383;
    int rest = i >> 14;
    int c16  = rest % 10;
    int n    = rest / 10;
    float v[16];
#pragma unroll
    for (int j = 0; j < 16; j++) {
        int ch = c16 * 16 + j;
        v[j] = (ch < 156) ? x[((size_t)n * 156 + ch) * HW + hw] : 0.f;
    }
    uint4 o0, o1;
    o0.x = h2u(v[0], v[1]);   o0.y = h2u(v[2], v[3]);
    o0.z = h2u(v[4], v[5]);   o0.w = h2u(v[6], v[7]);
    o1.x = h2u(v[8], v[9]);   o1.y = h2u(v[10], v[11]);
    o1.z = h2u(v[12], v[13]); o1.w = h2u(v[14], v[15]);
    uint4* dst = (uint4*)x16 + ((size_t)i) * 2;
    dst[0] = o0; dst[1] = o1;
}

__device__ __forceinline__ float apply_act(float v, int ACT) {
    if (ACT == 1) return fmaxf(v, 0.f);
    if (ACT == 2) return 1.f / (1.f + __expf(-v));
    return v;
}

// ---------------------------------------------------------------------------
// fp16 tensor-core 3x3 same-conv (mma.sync m16n8k16) on NHWC16.
// Block = (n, row h, MT co).  8 warps: wm=warp&3 -> 32-px span,
// wn=warp>>2 -> MT/2 co.  smem slab [3 rows][130 px][16ch], px stride 48B
// (16B-aligned for ldmatrix, bank-conflict-free).  A fragment = 1 ldmatrix.x4.
// B via __ldg (L1-resident).  Register-prefetch double buffer, 1 barrier/chunk.
// ---------------------------------------------------------------------------
template<int CIN, int COUT, int MT, int ACT, int CO_OFF, int CO_PAD, bool OUTF16, int NBLK>
__global__ __launch_bounds__(256, NBLK)
void convmma16(const unsigned* __restrict__ in, const unsigned* __restrict__ mw,
               const float* __restrict__ bias, void* __restrict__ outp) {
    constexpr int CHUNKS = (CIN + 15) / 16;
    constexpr int ROWW   = 130 * 12;         // u32 words per slab row (px stride 12)
    constexpr int BUFW   = 3 * ROWW;         // 4680 words = 18720 B
    constexpr int NT     = MT / 16;

    __shared__ unsigned s_in[2 * BUFW];      // 37440 B

    const int n    = blockIdx.z;
    const int h    = blockIdx.x;
    const int cob0 = CO_OFF + blockIdx.y * MT;
    const int tid  = threadIdx.x;
    const int lane = tid & 31;
    const int warp = tid >> 5;
    const int wm   = warp & 3;
    const int wn   = warp >> 2;
    const int r4   = lane & 3;
    const int r4h  = lane >> 2;
    const int pxb  = wm * 32;
    const int col  = wn * (MT / 2);

    const uint4* inN4 = (const uint4*)in + (size_t)n * CHUNKS * (HW * 2);

    // zero halo pixels (px_s 0 and 129, both 16B halves, 3 rows, 2 buffers)
    if (tid < 96) {
        int w  = tid & 7;
        int px = ((tid >> 3) & 1) ? 129 : 0;
        int r  = (tid >> 4) % 3;
        int b  = tid / 48;
        s_in[b * BUFW + r * ROWW + px * 12 + w] = 0u;
    }

    // staging slots: 768 uint4 = 3 per thread; warp-local (px, half) mapping
    int sm_off[3], g_off[3]; bool rowok[3];
#pragma unroll
    for (int jj = 0; jj < 3; jj++) {
        int j    = jj * 256 + tid;
        int row  = j >> 8;
        int i    = j & 255;
        int px   = ((i >> 5) << 4) + (i & 15);
        int half = (i >> 4) & 1;
        int gh   = h - 1 + row;
        rowok[jj]  = (gh >= 0 && gh < 128);
        sm_off[jj] = row * ROWW + (px + 1) * 12 + half * 4;
        g_off[jj]  = (rowok[jj] ? gh : 0) * 256 + px * 2 + half;
    }

    float C[2][NT][4];
#pragma unroll
    for (int mt = 0; mt < 2; mt++)
#pragma unroll
        for (int nt = 0; nt < NT; nt++)
#pragma unroll
            for (int k = 0; k < 4; k++) C[mt][nt][k] = 0.f;

    const unsigned sbase = (unsigned)__cvta_generic_to_shared((void*)s_in);
    const unsigned athr  = sbase + (unsigned)((pxb + (lane & 15)) * 48) + (lane & 16);

    uint4 pf[3];
#pragma unroll
    for (int jj = 0; jj < 3; jj++)
        pf[jj] = rowok[jj] ? inN4[g_off[jj]] : make_uint4(0, 0, 0, 0);

    for (int chunk = 0; chunk < CHUNKS; chunk++) {
        unsigned* buf = s_in + (chunk & 1) * BUFW;
#pragma unroll
        for (int jj = 0; jj < 3; jj++) *(uint4*)(buf + sm_off[jj]) = pf[jj];
        __syncthreads();

        if (chunk + 1 < CHUNKS) {
#pragma unroll
            for (int jj = 0; jj < 3; jj++)
                pf[jj] = rowok[jj]
                       ? inN4[(size_t)(chunk + 1) * (HW * 2) + g_off[jj]]
                       : make_uint4(0, 0, 0, 0);
        }

        const unsigned abuf = athr + (chunk & 1) * (BUFW * 4);
        const unsigned* wc = mw + (((size_t)chunk * 9) * CO_PAD + cob0 + col + r4h) * 8 + r4 * 2;

#pragma unroll
        for (int dh = 0; dh < 3; dh++) {
#pragma unroll
            for (int dw = 0; dw < 3; dw++) {
                const int tap = dh * 3 + dw;
                unsigned a0[4], a1[4];
                ldsm4(a0, abuf + dh * (ROWW * 4) + dw * 48);
                ldsm4(a1, abuf + dh * (ROWW * 4) + (dw + 16) * 48);
#pragma unroll
                for (int nt = 0; nt < NT; nt++) {
                    uint2 b = __ldg((const uint2*)(wc + ((size_t)tap * CO_PAD + nt * 8) * 8));
                    mma_f16(C[0][nt], a0, b);
                    mma_f16(C[1][nt], a1, b);
                }
            }
        }
    }

    // epilogue: c0 (px, co) c1 (px, co+1) c2 (px+8, co) c3 (px+8, co+1)
#pragma unroll
    for (int mt = 0; mt < 2; mt++) {
#pragma unroll
        for (int nt = 0; nt < NT; nt++) {
            int px = pxb + mt * 16 + r4h;
            int co = cob0 + col + nt * 8 + 2 * r4;
            if (OUTF16) {
                float b0 = bias[co], b1 = bias[co + 1];
                unsigned* op = (unsigned*)outp
                    + (((size_t)n * (COUT / 16) + (co >> 4)) * HW + h * 128 + px) * 8
                    + ((co & 15) >> 1);
                op[0]  = h2u(apply_act(C[mt][nt][0] + b0, ACT),
                             apply_act(C[mt][nt][1] + b1, ACT));
                op[64] = h2u(apply_act(C[mt][nt][2] + b0, ACT),
                             apply_act(C[mt][nt][3] + b1, ACT));
            } else {
#pragma unroll
                for (int half = 0; half < 2; half++) {
                    if (co + half < COUT) {
                        float b = bias[co + half];
                        float* op = (float*)outp + ((size_t)n * COUT + co + half) * HW
                                  + h * 128 + px;
                        op[0] = apply_act(C[mt][nt][half] + b, ACT);
                        op[8] = apply_act(C[mt][nt][2 + half] + b, ACT);
                    }
                }
            }
        }
    }
}

// ---------------------------------------------------------------------------
// Vector quantizer.  Vector = 8 consecutive W pixels of one channel.  Thread
// handles 4 channels (4cg..4cg+3) of one (n, h, wgroup) -> writes q NHWC16
// directly (uint2 data + uint2 zeros for ch 8..15).  Loss exact fp32.
// ---------------------------------------------------------------------------
__global__ __launch_bounds__(256)
void vq_kernel(const float* __restrict__ z, const float* __restrict__ emb,
               unsigned* __restrict__ q16, double* __restrict__ part) {
    __shared__ float  s_e[512 * 8];
    __shared__ float  s_hn[512];
    __shared__ double s_red[256];

    const int tid = threadIdx.x;
    for (int i = tid; i < 4096; i += 256) s_e[i] = emb[i];
    __syncthreads();
    for (int k = tid; k < 512; k += 256) {
        float s = 0.f;
#pragma unroll
        for (int j = 0; j < 8; j++) { float e = s_e[k * 8 + j]; s += e * e; }
        s_hn[k] = 0.5f * s;
    }
    __syncthreads();

    const int ti = blockIdx.x * 256 + tid;
    const int wg = ti & 15;
    const int hh = (ti >> 4) & 127;
    const int cg = (ti >> 11) & 1;
    const int nn = ti >> 12;

    float v[4][8];
#pragma unroll
    for (int e = 0; e < 4; e++) {
        int vi = (((nn * 8 + 4 * cg + e) * 128) + hh) * 16 + wg;
        float4 a = ((const float4*)z)[vi * 2];
        float4 b = ((const float4*)z)[vi * 2 + 1];
        v[e][0] = a.x; v[e][1] = a.y; v[e][2] = a.z; v[e][3] = a.w;
        v[e][4] = b.x; v[e][5] = b.y; v[e][6] = b.z; v[e][7] = b.w;
    }

    float best[4] = {3.4e38f, 3.4e38f, 3.4e38f, 3.4e38f};
    int   bk[4]   = {0, 0, 0, 0};
    for (int k = 0; k < 512; k++) {
        float e0 = s_e[k * 8 + 0], e1 = s_e[k * 8 + 1], e2 = s_e[k * 8 + 2], e3 = s_e[k * 8 + 3];
        float e4 = s_e[k * 8 + 4], e5 = s_e[k * 8 + 5], e6 = s_e[k * 8 + 6], e7 = s_e[k * 8 + 7];
        float hn = s_hn[k];
#pragma unroll
        for (int u = 0; u < 4; u++) {
            float dot = e0 * v[u][0] + e1 * v[u][1] + e2 * v[u][2] + e3 * v[u][3]
                      + e4 * v[u][4] + e5 * v[u][5] + e6 * v[u][6] + e7 * v[u][7];
            float sc = hn - dot;
            if (sc < best[u]) { best[u] = sc; bk[u] = k; }
        }
    }

    float sq = 0.f;
#pragma unroll
    for (int u = 0; u < 4; u++)
#pragma unroll
        for (int j = 0; j < 8; j++) {
            float d = s_e[bk[u] * 8 + j] - v[u][j];
            sq += d * d;
        }

    // write q NHWC16: ch (4cg..4cg+3) data + zeros for ch (8+4cg..11+4cg)
    size_t pxbase = (size_t)nn * HW + hh * 128 + wg * 8;
#pragma unroll
    for (int p = 0; p < 8; p++) {
        uint2 d;
        d.x = h2u(s_e[bk[0] * 8 + p], s_e[bk[1] * 8 + p]);
        d.y = h2u(s_e[bk[2] * 8 + p], s_e[bk[3] * 8 + p]);
        unsigned* qp = q16 + (pxbase + p) * 8 + cg * 2;
        *(uint2*)qp       = d;
        *(uint2*)(qp + 4) = make_uint2(0u, 0u);
    }

    s_red[tid] = (double)sq;
    __syncthreads();
    for (int o = 128; o > 0; o >>= 1) {
        if (tid < o) s_red[tid] += s_red[tid + o];
        __syncthreads();
    }
    if (tid == 0) part[blockIdx.x] = s_red[0];
}

__global__ void finalize_loss(const double* __restrict__ part, float* __restrict__ outp) {
    __shared__ double s[256];
    int tid = threadIdx.x;
    s[tid] = part[tid];
    __syncthreads();
    for (int o = 128; o > 0; o >>= 1) {
        if (tid < o) s[tid] += s[tid + o];
        __syncthreads();
    }
    if (tid == 0) *outp = (float)(1.25 * s[0] / 2097152.0);
}

// ---------------------------------------------------------------------------
extern "C" void kernel_launch(void* const* d_in, const int* in_sizes, int n_in,
                              void* d_out, int out_size) {
    (void)in_sizes; (void)n_in;
    const float* x   = (const float*)d_in[0];
    const float* e1w = (const float*)d_in[1];
    const float* e1b = (const float*)d_in[2];
    const float* e2w = (const float*)d_in[3];
    const float* e2b = (const float*)d_in[4];
    const float* e3w = (const float*)d_in[5];
    const float* e3b = (const float*)d_in[6];
    const float* emb = (const float*)d_in[7];
    const float* d1w = (const float*)d_in[8];
    const float* d1b = (const float*)d_in[9];
    const float* d2w = (const float*)d_in[10];
    const float* d2b = (const float*)d_in[11];
    const float* d3w = (const float*)d_in[12];
    const float* d3b = (const float*)d_in[13];
    float* out = (float*)d_out;

    void *x16, *z1h, *z2h, *z3, *qh, *y1h, *y2h, *part;
    void *we1, *we2, *we3, *wd1, *wd2, *wd3;
    cudaGetSymbolAddress(&x16, g_x16);
    cudaGetSymbolAddress(&z1h, g_z1h);
    cudaGetSymbolAddress(&z2h, g_z2h);
    cudaGetSymbolAddress(&z3,  g_z3);
    cudaGetSymbolAddress(&qh,  g_qh);
    cudaGetSymbolAddress(&y1h, g_y1h);
    cudaGetSymbolAddress(&y2h, g_y2h);
    cudaGetSymbolAddress(&we1, g_w_e1);
    cudaGetSymbolAddress(&we2, g_w_e2);
    cudaGetSymbolAddress(&we3, g_w_e3);
    cudaGetSymbolAddress(&wd1, g_w_d1);
    cudaGetSymbolAddress(&wd2, g_w_d2);
    cudaGetSymbolAddress(&wd3, g_w_d3);
    cudaGetSymbolAddress(&part, g_part);

    // ---- weight packing + x conversion
    pack_all<<<(267264 + 255) / 256, 256>>>(
        e1w, e2w, e3w, d1w, d2w, d3w,
        (unsigned*)we1, (unsigned*)we2, (unsigned*)we3,
        (unsigned*)wd1, (unsigned*)wd2, (unsigned*)wd3);
    x_to_nhwc<<<(BATCH * 10 * HW + 255) / 256, 256>>>(x, (unsigned*)x16);

    // encoder (fp16 tensor path, NHWC16)
    convmma16<156, 128, 128, 1, 0, 128, true, 2>
        <<<dim3(128, 1, 16), 256>>>((unsigned*)x16, (unsigned*)we1, e1b, z1h);
    convmma16<128,  64,  64, 1, 0,  64, true, 3>
        <<<dim3(128, 1, 16), 256>>>((unsigned*)z1h, (unsigned*)we2, e2b, z2h);
    convmma16< 64,   8,  16, 1, 0,  16, false, 3>
        <<<dim3(128, 1, 16), 256>>>((unsigned*)z2h, (unsigned*)we3, e3b, z3);

    // vector quantizer + loss partials (exact fp32; q emitted NHWC16)
    vq_kernel<<<256, 256>>>((const float*)z3, emb, (unsigned*)qh, (double*)part);

    // decoder (fp16 tensor path, NHWC16)
    convmma16<  8,  64,  64, 1, 0,  64, true, 3>
        <<<dim3(128, 1, 16), 256>>>((unsigned*)qh,  (unsigned*)wd1, d1b, y1h);
    convmma16< 64, 128, 128, 1, 0, 128, true, 2>
        <<<dim3(128, 1, 16), 256>>>((unsigned*)y1h, (unsigned*)wd2, d2b, y2h);
    convmma16<128, 156, 160, 2, 0, 160, false, 2>
        <<<dim3(128, 1, 16), 256>>>((unsigned*)y2h, (unsigned*)wd3, d3b, out);

    finalize_loss<<<1, 256>>>((const double*)part, out + (out_size - 1));
}

// round 16
// speedup vs baseline: 1.6769x; 1.6769x over previous
#include <cuda_runtime.h>
#include <cuda_fp16.h>
#include <math.h>

// ---------------------------------------------------------------------------
// VQ-VAE forward.  B=16, L=156, P=8, H=W=128, codebook 512x8.
// R16: revert d3 to MT=80 x grid.y=2 (R15 NT=10 spilled); add ROWS=2 mode
//      (4-row slab, 2 output rows) for e2/d1/e3 -- staging/barriers per
//      output cut, C=64 regs fits NBLK=2.  Bit-identical numerics to R14.
// ---------------------------------------------------------------------------

#define BATCH 16
#define HW    16384   // 128*128

__device__ __forceinline__ void mma_f16(float c[4], const unsigned a[4], uint2 b) {
    asm volatile("mma.sync.aligned.m16n8k16.row.col.f32.f16.f16.f32 "
        "{%0,%1,%2,%3}, {%4,%5,%6,%7}, {%8,%9}, {%0,%1,%2,%3};"
        : "+f"(c[0]), "+f"(c[1]), "+f"(c[2]), "+f"(c[3])
        : "r"(a[0]), "r"(a[1]), "r"(a[2]), "r"(a[3]), "r"(b.x), "r"(b.y));
}
__device__ __forceinline__ void ldsm4(unsigned a[4], unsigned addr) {
    asm volatile("ldmatrix.sync.aligned.m8n8.x4.shared.b16 {%0,%1,%2,%3}, [%4];"
        : "=r"(a[0]), "=r"(a[1]), "=r"(a[2]), "=r"(a[3]) : "r"(addr));
}
__device__ __forceinline__ unsigned h2u(float lo, float hi) {
    __half2 h = __floats2half2_rn(lo, hi);
    return *(unsigned*)&h;
}

// Static device scratch.  Activations NHWC16: [n][chunk][h][w][16ch] fp16,
// stored as u32 (half2); 8 u32 per pixel per chunk.
__device__ unsigned g_x16[BATCH * 10 * HW * 8];
__device__ unsigned g_z1h[BATCH *  8 * HW * 8];
__device__ unsigned g_z2h[BATCH *  4 * HW * 8];
__device__ float    g_z3 [BATCH *  8 * HW];      // fp32 NCHW for VQ
__device__ unsigned g_qh [BATCH *  1 * HW * 8];  // ch 8..15 zeroed by VQ
__device__ unsigned g_y1h[BATCH *  4 * HW * 8];
__device__ unsigned g_y2h[BATCH *  8 * HW * 8];
// fp16 weights: [chunk16][tap 9][CO_PAD][slot 8]; slot s -> ci pair
// (2p, 2p+1), p = (s&1)?(s>>1)+4:(s>>1)  (matches mma B fragment k-order).
__device__ unsigned g_w_e1[10 * 9 * 128 * 8];
__device__ unsigned g_w_e2[ 8 * 9 *  64 * 8];
__device__ unsigned g_w_e3[ 4 * 9 *  16 * 8];
__device__ unsigned g_w_d1[ 1 * 9 *  64 * 8];
__device__ unsigned g_w_d2[ 4 * 9 * 128 * 8];
__device__ unsigned g_w_d3[ 8 * 9 * 160 * 8];
__device__ double   g_part[256];

// ---------------------------------------------------------------------------
__device__ void pack16(const float* __restrict__ w, unsigned* __restrict__ out,
                       int CIN, int COUT, int CO_PAD, int transposed, int idx) {
    int s     = idx & 7;
    int co    = (idx >> 3) % CO_PAD;
    int tap   = ((idx >> 3) / CO_PAD) % 9;
    int chunk = ((idx >> 3) / CO_PAD) / 9;
    int p     = (s & 1) ? (s >> 1) + 4 : (s >> 1);
    int ci0   = chunk * 16 + 2 * p, ci1 = ci0 + 1;
    float v0 = 0.f, v1 = 0.f;
    if (co < COUT) {
        if (transposed) {
            if (ci0 < CIN) v0 = w[((size_t)ci0 * COUT + co) * 9 + (8 - tap)];
            if (ci1 < CIN) v1 = w[((size_t)ci1 * COUT + co) * 9 + (8 - tap)];
        } else {
            if (ci0 < CIN) v0 = w[((size_t)co * CIN + ci0) * 9 + tap];
            if (ci1 < CIN) v1 = w[((size_t)co * CIN + ci1) * 9 + tap];
        }
    }
    out[idx] = h2u(v0, v1);
}

__global__ void pack_all(const float* e1w, const float* e2w, const float* e3w,
                         const float* d1w, const float* d2w, const float* d3w,
                         unsigned* we1, unsigned* we2, unsigned* we3,
                         unsigned* wd1, unsigned* wd2, unsigned* wd3) {
    int idx = blockIdx.x * 256 + threadIdx.x;
    if (idx < 92160) { pack16(e1w, we1, 156, 128, 128, 0, idx); return; }
    idx -= 92160;
    if (idx < 36864) { pack16(e2w, we2, 128,  64,  64, 0, idx); return; }
    idx -= 36864;
    if (idx < 4608)  { pack16(e3w, we3,  64,   8,  16, 0, idx); return; }
    idx -= 4608;
    if (idx < 4608)  { pack16(d1w, wd1,   8,  64,  64, 1, idx); return; }
    idx -= 4608;
    if (idx < 36864) { pack16(d2w, wd2,  64, 128, 128, 1, idx); return; }
    idx -= 36864;
    if (idx < 92160) { pack16(d3w, wd3, 128, 156, 160, 1, idx); }
}

// x (fp32 NCHW, 156 ch) -> NHWC16 fp16, ch 156..159 zero.
__global__ void x_to_nhwc(const float* __restrict__ x, unsigned* __restrict__ x16) {
    int i = blockIdx.x * 256 + threadIdx.x;
    const int total = BATCH * 10 * HW;
    if (i >= total) return;
    int hw   = i & 16383;
    int rest = i >> 14;
    int c16  = rest % 10;
    int n    = rest / 10;
    float v[16];
#pragma unroll
    for (int j = 0; j < 16; j++) {
        int ch = c16 * 16 + j;
        v[j] = (ch < 156) ? x[((size_t)n * 156 + ch) * HW + hw] : 0.f;
    }
    uint4 o0, o1;
    o0.x = h2u(v[0], v[1]);   o0.y = h2u(v[2], v[3]);
    o0.z = h2u(v[4], v[5]);   o0.w = h2u(v[6], v[7]);
    o1.x = h2u(v[8], v[9]);   o1.y = h2u(v[10], v[11]);
    o1.z = h2u(v[12], v[13]); o1.w = h2u(v[14], v[15]);
    uint4* dst = (uint4*)x16 + ((size_t)i) * 2;
    dst[0] = o0; dst[1] = o1;
}

__device__ __forceinline__ float apply_act(float v, int ACT) {
    if (ACT == 1) return fmaxf(v, 0.f);
    if (ACT == 2) return 1.f / (1.f + __expf(-v));
    return v;
}

// ---------------------------------------------------------------------------
// fp16 tensor-core 3x3 same-conv (mma.sync m16n8k16) on NHWC16.
// Block = (n, ROWS output rows at h0, MT co).  8 warps: wm=warp&3 -> 32-px,
// wn=warp>>2 -> MT/2 co.  Slab = ROWS+2 input rows x 130 px x 16ch, px stride
// 48B (ldmatrix-aligned, bank-conflict-free).  A fragment = 1 ldmatrix.x4 per
// (slab row, dw), shared by all output rows using it.  Per-output tap order
// = dh asc, dw asc -- identical to the ROWS=1 kernel (bit-identical results).
// B via __ldg.  Register-prefetch double buffer, one __syncthreads per chunk.
// ---------------------------------------------------------------------------
template<int ROWS, int CIN, int COUT, int MT, int ACT, int CO_OFF, int CO_PAD,
         bool OUTF16, int NBLK>
__global__ __launch_bounds__(256, NBLK)
void convmma16(const unsigned* __restrict__ in, const unsigned* __restrict__ mw,
               const float* __restrict__ bias, void* __restrict__ outp) {
    constexpr int CHUNKS = (CIN + 15) / 16;
    constexpr int SLOTS  = ROWS + 2;
    constexpr int ROWW   = 130 * 12;          // u32 words per slab row
    constexpr int BUFW   = SLOTS * ROWW;
    constexpr int NT     = MT / 16;

    extern __shared__ unsigned s_in[];        // [2][BUFW]

    const int n    = blockIdx.z;
    const int h0   = blockIdx.x * ROWS;
    const int cob0 = CO_OFF + blockIdx.y * MT;
    const int tid  = threadIdx.x;
    const int lane = tid & 31;
    const int warp = tid >> 5;
    const int wm   = warp & 3;
    const int wn   = warp >> 2;
    const int r4   = lane & 3;
    const int r4h  = lane >> 2;
    const int pxb  = wm * 32;
    const int col  = wn * (MT / 2);

    const uint4* inN4 = (const uint4*)in + (size_t)n * CHUNKS * (HW * 2);

    // zero halo pixels (px_s 0 and 129, both 16B halves, SLOTS rows, 2 bufs)
    if (tid < 32 * SLOTS) {
        int w  = tid & 7;
        int px = ((tid >> 3) & 1) ? 129 : 0;
        int r  = (tid >> 4) % SLOTS;
        int b  = tid / (16 * SLOTS);
        s_in[b * BUFW + r * ROWW + px * 12 + w] = 0u;
    }

    // staging slots: SLOTS*256 uint4 = SLOTS per thread
    int sm_off[SLOTS], g_off[SLOTS]; bool rowok[SLOTS];
#pragma unroll
    for (int jj = 0; jj < SLOTS; jj++) {
        int j    = jj * 256 + tid;
        int row  = j >> 8;
        int i    = j & 255;
        int px   = ((i >> 5) << 4) + (i & 15);
        int half = (i >> 4) & 1;
        int gh   = h0 - 1 + row;
        rowok[jj]  = (gh >= 0 && gh < 128);
        sm_off[jj] = row * ROWW + (px + 1) * 12 + half * 4;
        g_off[jj]  = (rowok[jj] ? gh : 0) * 256 + px * 2 + half;
    }

    float C[ROWS][2][NT][4];
#pragma unroll
    for (int r = 0; r < ROWS; r++)
#pragma unroll
        for (int mt = 0; mt < 2; mt++)
#pragma unroll
            for (int nt = 0; nt < NT; nt++)
#pragma unroll
                for (int k = 0; k < 4; k++) C[r][mt][nt][k] = 0.f;

    const unsigned sbase = (unsigned)__cvta_generic_to_shared((void*)s_in);
    const unsigned athr  = sbase + (unsigned)((pxb + (lane & 15)) * 48) + (lane & 16);

    uint4 pf[SLOTS];
#pragma unroll
    for (int jj = 0; jj < SLOTS; jj++)
        pf[jj] = rowok[jj] ? inN4[g_off[jj]] : make_uint4(0, 0, 0, 0);

    for (int chunk = 0; chunk < CHUNKS; chunk++) {
        unsigned* buf = s_in + (chunk & 1) * BUFW;
#pragma unroll
        for (int jj = 0; jj < SLOTS; jj++) *(uint4*)(buf + sm_off[jj]) = pf[jj];
        __syncthreads();

        if (chunk + 1 < CHUNKS) {
#pragma unroll
            for (int jj = 0; jj < SLOTS; jj++)
                pf[jj] = rowok[jj]
                       ? inN4[(size_t)(chunk + 1) * (HW * 2) + g_off[jj]]
                       : make_uint4(0, 0, 0, 0);
        }

        const unsigned abuf = athr + (chunk & 1) * (BUFW * 4);
        const unsigned* wc = mw + (((size_t)chunk * 9) * CO_PAD + cob0 + col + r4h) * 8 + r4 * 2;

#pragma unroll
        for (int sr = 0; sr < SLOTS; sr++) {
#pragma unroll
            for (int dw = 0; dw < 3; dw++) {
                unsigned a0[4], a1[4];
                ldsm4(a0, abuf + sr * (ROWW * 4) + dw * 48);
                ldsm4(a1, abuf + sr * (ROWW * 4) + (dw + 16) * 48);
#pragma unroll
                for (int r = (sr - 2 < 0 ? 0 : sr - 2);
                         r <= (sr < ROWS - 1 ? sr : ROWS - 1); r++) {
                    const int tap = (sr - r) * 3 + dw;
#pragma unroll
                    for (int nt = 0; nt < NT; nt++) {
                        uint2 b = __ldg((const uint2*)(wc + ((size_t)tap * CO_PAD + nt * 8) * 8));
                        mma_f16(C[r][0][nt], a0, b);
                        mma_f16(C[r][1][nt], a1, b);
                    }
                }
            }
        }
    }

    // epilogue: c0 (px, co) c1 (px, co+1) c2 (px+8, co) c3 (px+8, co+1)
#pragma unroll
    for (int r = 0; r < ROWS; r++) {
        const int h = h0 + r;
#pragma unroll
        for (int mt = 0; mt < 2; mt++) {
#pragma unroll
            for (int nt = 0; nt < NT; nt++) {
                int px = pxb + mt * 16 + r4h;
                int co = cob0 + col + nt * 8 + 2 * r4;
                if (OUTF16) {
                    float b0 = bias[co], b1 = bias[co + 1];
                    unsigned* op = (unsigned*)outp
                        + (((size_t)n * (COUT / 16) + (co >> 4)) * HW + h * 128 + px) * 8
                        + ((co & 15) >> 1);
                    op[0]  = h2u(apply_act(C[r][mt][nt][0] + b0, ACT),
                                 apply_act(C[r][mt][nt][1] + b1, ACT));
                    op[64] = h2u(apply_act(C[r][mt][nt][2] + b0, ACT),
                                 apply_act(C[r][mt][nt][3] + b1, ACT));
                } else {
#pragma unroll
                    for (int half = 0; half < 2; half++) {
                        if (co + half < COUT) {
                            float b = bias[co + half];
                            float* op = (float*)outp + ((size_t)n * COUT + co + half) * HW
                                      + h * 128 + px;
                            op[0] = apply_act(C[r][mt][nt][half] + b, ACT);
                            op[8] = apply_act(C[r][mt][nt][2 + half] + b, ACT);
                        }
                    }
                }
            }
        }
    }
}

// ---------------------------------------------------------------------------
// Vector quantizer.  Vector = 8 consecutive W pixels of one channel.  Thread
// handles 4 channels (4cg..4cg+3) of one (n, h, wgroup) -> writes q NHWC16
// directly (uint2 data + uint2 zeros for ch 8..15).  Loss exact fp32.
// ---------------------------------------------------------------------------
__global__ __launch_bounds__(256)
void vq_kernel(const float* __restrict__ z, const float* __restrict__ emb,
               unsigned* __restrict__ q16, double* __restrict__ part) {
    __shared__ float  s_e[512 * 8];
    __shared__ float  s_hn[512];
    __shared__ double s_red[256];

    const int tid = threadIdx.x;
    for (int i = tid; i < 4096; i += 256) s_e[i] = emb[i];
    __syncthreads();
    for (int k = tid; k < 512; k += 256) {
        float s = 0.f;
#pragma unroll
        for (int j = 0; j < 8; j++) { float e = s_e[k * 8 + j]; s += e * e; }
        s_hn[k] = 0.5f * s;
    }
    __syncthreads();

    const int ti = blockIdx.x * 256 + tid;
    const int wg = ti & 15;
    const int hh = (ti >> 4) & 127;
    const int cg = (ti >> 11) & 1;
    const int nn = ti >> 12;

    float v[4][8];
#pragma unroll
    for (int e = 0; e < 4; e++) {
        int vi = (((nn * 8 + 4 * cg + e) * 128) + hh) * 16 + wg;
        float4 a = ((const float4*)z)[vi * 2];
        float4 b = ((const float4*)z)[vi * 2 + 1];
        v[e][0] = a.x; v[e][1] = a.y; v[e][2] = a.z; v[e][3] = a.w;
        v[e][4] = b.x; v[e][5] = b.y; v[e][6] = b.z; v[e][7] = b.w;
    }

    float best[4] = {3.4e38f, 3.4e38f, 3.4e38f, 3.4e38f};
    int   bk[4]   = {0, 0, 0, 0};
    for (int k = 0; k < 512; k++) {
        float e0 = s_e[k * 8 + 0], e1 = s_e[k * 8 + 1], e2 = s_e[k * 8 + 2], e3 = s_e[k * 8 + 3];
        float e4 = s_e[k * 8 + 4], e5 = s_e[k * 8 + 5], e6 = s_e[k * 8 + 6], e7 = s_e[k * 8 + 7];
        float hn = s_hn[k];
#pragma unroll
        for (int u = 0; u < 4; u++) {
            float dot = e0 * v[u][0] + e1 * v[u][1] + e2 * v[u][2] + e3 * v[u][3]
                      + e4 * v[u][4] + e5 * v[u][5] + e6 * v[u][6] + e7 * v[u][7];
            float sc = hn - dot;
            if (sc < best[u]) { best[u] = sc; bk[u] = k; }
        }
    }

    float sq = 0.f;
#pragma unroll
    for (int u = 0; u < 4; u++)
#pragma unroll
        for (int j = 0; j < 8; j++) {
            float d = s_e[bk[u] * 8 + j] - v[u][j];
            sq += d * d;
        }

    // write q NHWC16: ch (4cg..4cg+3) data + zeros for ch (8+4cg..11+4cg)
    size_t pxbase = (size_t)nn * HW + hh * 128 + wg * 8;
#pragma unroll
    for (int p = 0; p < 8; p++) {
        uint2 d;
        d.x = h2u(s_e[bk[0] * 8 + p], s_e[bk[1] * 8 + p]);
        d.y = h2u(s_e[bk[2] * 8 + p], s_e[bk[3] * 8 + p]);
        unsigned* qp = q16 + (pxbase + p) * 8 + cg * 2;
        *(uint2*)qp       = d;
        *(uint2*)(qp + 4) = make_uint2(0u, 0u);
    }

    s_red[tid] = (double)sq;
    __syncthreads();
    for (int o = 128; o > 0; o >>= 1) {
        if (tid < o) s_red[tid] += s_red[tid + o];
        __syncthreads();
    }
    if (tid == 0) part[blockIdx.x] = s_red[0];
}

__global__ void finalize_loss(const double* __restrict__ part, float* __restrict__ outp) {
    __shared__ double s[256];
    int tid = threadIdx.x;
    s[tid] = part[tid];
    __syncthreads();
    for (int o = 128; o > 0; o >>= 1) {
        if (tid < o) s[tid] += s[tid + o];
        __syncthreads();
    }
    if (tid == 0) *outp = (float)(1.25 * s[0] / 2097152.0);
}

// ---------------------------------------------------------------------------
extern "C" void kernel_launch(void* const* d_in, const int* in_sizes, int n_in,
                              void* d_out, int out_size) {
    (void)in_sizes; (void)n_in;
    const float* x   = (const float*)d_in[0];
    const float* e1w = (const float*)d_in[1];
    const float* e1b = (const float*)d_in[2];
    const float* e2w = (const float*)d_in[3];
    const float* e2b = (const float*)d_in[4];
    const float* e3w = (const float*)d_in[5];
    const float* e3b = (const float*)d_in[6];
    const float* emb = (const float*)d_in[7];
    const float* d1w = (const float*)d_in[8];
    const float* d1b = (const float*)d_in[9];
    const float* d2w = (const float*)d_in[10];
    const float* d2b = (const float*)d_in[11];
    const float* d3w = (const float*)d_in[12];
    const float* d3b = (const float*)d_in[13];
    float* out = (float*)d_out;

    void *x16, *z1h, *z2h, *z3, *qh, *y1h, *y2h, *part;
    void *we1, *we2, *we3, *wd1, *wd2, *wd3;
    cudaGetSymbolAddress(&x16, g_x16);
    cudaGetSymbolAddress(&z1h, g_z1h);
    cudaGetSymbolAddress(&z2h, g_z2h);
    cudaGetSymbolAddress(&z3,  g_z3);
    cudaGetSymbolAddress(&qh,  g_qh);
    cudaGetSymbolAddress(&y1h, g_y1h);
    cudaGetSymbolAddress(&y2h, g_y2h);
    cudaGetSymbolAddress(&we1, g_w_e1);
    cudaGetSymbolAddress(&we2, g_w_e2);
    cudaGetSymbolAddress(&we3, g_w_e3);
    cudaGetSymbolAddress(&wd1, g_w_d1);
    cudaGetSymbolAddress(&wd2, g_w_d2);
    cudaGetSymbolAddress(&wd3, g_w_d3);
    cudaGetSymbolAddress(&part, g_part);

    // smem bytes: 2 * (ROWS+2) * 1560 * 4
    const int SM_R1 = 2 * 3 * 1560 * 4;   // 37440
    const int SM_R2 = 2 * 4 * 1560 * 4;   // 49920

    static bool attr_done = false;
    if (!attr_done) {
        attr_done = true;
        cudaFuncSetAttribute((const void*)convmma16<1, 156, 128, 128, 1, 0, 128, true, 2>,
                             cudaFuncAttributeMaxDynamicSharedMemorySize, SM_R1);
        cudaFuncSetAttribute((const void*)convmma16<2, 128, 64, 64, 1, 0, 64, true, 2>,
                             cudaFuncAttributeMaxDynamicSharedMemorySize, SM_R2);
        cudaFuncSetAttribute((const void*)convmma16<2, 64, 8, 16, 1, 0, 16, false, 2>,
                             cudaFuncAttributeMaxDynamicSharedMemorySize, SM_R2);
        cudaFuncSetAttribute((const void*)convmma16<2, 8, 64, 64, 1, 0, 64, true, 2>,
                             cudaFuncAttributeMaxDynamicSharedMemorySize, SM_R2);
        cudaFuncSetAttribute((const void*)convmma16<1, 64, 128, 128, 1, 0, 128, true, 2>,
                             cudaFuncAttributeMaxDynamicSharedMemorySize, SM_R1);
        cudaFuncSetAttribute((const void*)convmma16<1, 128, 156, 80, 2, 0, 160, false, 2>,
                             cudaFuncAttributeMaxDynamicSharedMemorySize, SM_R1);
    }

    // ---- weight packing + x conversion
    pack_all<<<(267264 + 255) / 256, 256>>>(
        e1w, e2w, e3w, d1w, d2w, d3w,
        (unsigned*)we1, (unsigned*)we2, (unsigned*)we3,
        (unsigned*)wd1, (unsigned*)wd2, (unsigned*)wd3);
    x_to_nhwc<<<(BATCH * 10 * HW + 255) / 256, 256>>>(x, (unsigned*)x16);

    // encoder (fp16 tensor path, NHWC16)
    convmma16<1, 156, 128, 128, 1, 0, 128, true, 2>
        <<<dim3(128, 1, 16), 256, SM_R1>>>((unsigned*)x16, (unsigned*)we1, e1b, z1h);
    convmma16<2, 128,  64,  64, 1, 0,  64, true, 2>
        <<<dim3( 64, 1, 16), 256, SM_R2>>>((unsigned*)z1h, (unsigned*)we2, e2b, z2h);
    convmma16<2,  64,   8,  16, 1, 0,  16, false, 2>
        <<<dim3( 64, 1, 16), 256, SM_R2>>>((unsigned*)z2h, (unsigned*)we3, e3b, z3);

    // vector quantizer + loss partials (exact fp32; q emitted NHWC16)
    vq_kernel<<<256, 256>>>((const float*)z3, emb, (unsigned*)qh, (double*)part);

    // decoder (fp16 tensor path, NHWC16)
    convmma16<2,   8,  64,  64, 1, 0,  64, true, 2>
        <<<dim3( 64, 1, 16), 256, SM_R2>>>((unsigned*)qh,  (unsigned*)wd1, d1b, y1h);
    convmma16<1,  64, 128, 128, 1, 0, 128, true, 2>
        <<<dim3(128, 1, 16), 256, SM_R1>>>((unsigned*)y1h, (unsigned*)wd2, d2b, y2h);
    convmma16<1, 128, 156,  80, 2, 0, 160, false, 2>
        <<<dim3(128, 2, 16), 256, SM_R1>>>((unsigned*)y2h, (unsigned*)wd3, d3b, out);

    finalize_loss<<<1, 256>>>((const double*)part, out + (out_size - 1));
}